// round 10
// baseline (speedup 1.0000x reference)
#include <cuda_runtime.h>
#include <stdint.h>

// ---------------------------------------------------------------------------
// TripletContrastiveLoss — tf32 mma.sync, 128x128 tile, occ-2, cp.async
// double buffer, permuted-K smem layout for vectorized LDS.64 fragment loads.
// (tcgen05 unavailable: bench PTX targets compute_103 w/o 'a'.)
// ---------------------------------------------------------------------------

#define BMAX 8192
#define DMAX 1024
#define INFBITS 0x7f800000u

#define BM 128
#define BN 128
#define BK 32
#define ASTR 40      // row stride (floats); 8*qid+2*qlane banks conflict-free for LDS.64
#define NTHR 256
#define SAE (BM * ASTR)                    // 5120 floats per buffer
#define SMEM4_BYTES (4 * SAE * 4 + BN * 4) // 2 stages x (A+B) + labels = 82432 B

// K-permutation: within every 8-float K-group, storage order is
// (k0,k4,k1,k5,k2,k6,k3,k7). Fragment pair (k, k+4) is then 8B-contiguous
// at float offset  g*8 + 2*(k%4)  for k-step group g.
__device__ float g_A[(size_t)BMAX * DMAX];   // normalized anchors (tf32, K-permuted)
__device__ float g_F[(size_t)BMAX * DMAX];   // normalized fields  (tf32, K-permuted)
__device__ int   g_aRow[BMAX];
__device__ int   g_fRow[BMAX];
__device__ int   g_aLab[BMAX];
__device__ int   g_fLab[BMAX];
__device__ int   g_aCnt;
__device__ int   g_fCnt;
__device__ unsigned g_posBits[BMAX];
__device__ unsigned g_negBits[BMAX];
__device__ int   g_is64;

__device__ __forceinline__ uint32_t smem_u32(const void* p) {
    uint32_t a;
    asm("{ .reg .u64 t; cvta.to.shared.u64 t, %1; cvt.u32.u64 %0, t; }"
        : "=r"(a) : "l"(p));
    return a;
}
__device__ __forceinline__ void cpa16(uint32_t dst, const void* src) {
    asm volatile("cp.async.cg.shared.global [%0], [%1], 16;"
                 :: "r"(dst), "l"(src));
}

// ---- K0: reset scalars --------------------------------------------------
__global__ void k0_reset() {
    g_aCnt = 0;
    g_fCnt = 0;
    g_is64 = 1;
}

// ---- K1: init min arrays + label dtype detection ------------------------
// int64 labels (<2^31): every odd 32-bit word is 0. int32: some odd word !=0.
__global__ void k1_init_detect(const unsigned* __restrict__ labw, int B) {
    int i = blockIdx.x * blockDim.x + threadIdx.x;
    if (i < B) {
        g_posBits[i] = INFBITS;
        g_negBits[i] = INFBITS;
        if ((i & 1) && labw[i] != 0u) g_is64 = 0;
    }
}

// ---- K2: partition into compact anchor/field lists ----------------------
__global__ void k2_partition(const void* __restrict__ labels,
                             const void* __restrict__ doms, int B) {
    int i = blockIdx.x * blockDim.x + threadIdx.x;
    if (i >= B) return;
    int is64 = g_is64;
    long long dom, lab;
    if (is64) {
        dom = ((const long long*)doms)[i];
        lab = ((const long long*)labels)[i];
    } else {
        dom = ((const int*)doms)[i];
        lab = ((const int*)labels)[i];
    }
    if (dom == 0) {
        int p = atomicAdd(&g_aCnt, 1);
        g_aRow[p] = i;
        g_aLab[p] = (int)lab;
    } else if (dom == 1) {
        int p = atomicAdd(&g_fCnt, 1);
        g_fRow[p] = i;
        g_fLab[p] = (int)lab;
    }
}

// ---- K3: normalize + tf32 round + K-permute, one warp per row -----------
__global__ void k3_normalize(const float* __restrict__ feat, int D) {
    int side = blockIdx.y;
    int n = side ? g_fCnt : g_aCnt;
    int warp = threadIdx.x >> 5;
    int lane = threadIdx.x & 31;
    int b = blockIdx.x * 8 + warp;
    if (b >= n) return;
    int row = side ? g_fRow[b] : g_aRow[b];
    const float4* src = (const float4*)(feat + (size_t)row * D);
    uint4* dst = (uint4*)((side ? g_F : g_A) + (size_t)b * D);
    int ng = D >> 3;                 // 8-float K-groups (<=128)

    float4 u[4], w[4];
    float s = 0.f;
    #pragma unroll
    for (int j = 0; j < 4; j++) {
        int g = lane + j * 32;
        if (g < ng) {
            u[j] = src[2 * g];
            w[j] = src[2 * g + 1];
            s += u[j].x * u[j].x + u[j].y * u[j].y + u[j].z * u[j].z + u[j].w * u[j].w;
            s += w[j].x * w[j].x + w[j].y * w[j].y + w[j].z * w[j].z + w[j].w * w[j].w;
        }
    }
    #pragma unroll
    for (int o = 16; o; o >>= 1) s += __shfl_xor_sync(0xffffffffu, s, o);
    float scale = 1.f / fmaxf(sqrtf(s), 1e-12f);

    #pragma unroll
    for (int j = 0; j < 4; j++) {
        int g = lane + j * 32;
        if (g < ng) {
            // permuted: (k0,k4,k1,k5) and (k2,k6,k3,k7)
            uint4 o0, o1;
            asm("cvt.rna.tf32.f32 %0, %1;" : "=r"(o0.x) : "f"(u[j].x * scale));
            asm("cvt.rna.tf32.f32 %0, %1;" : "=r"(o0.y) : "f"(w[j].x * scale));
            asm("cvt.rna.tf32.f32 %0, %1;" : "=r"(o0.z) : "f"(u[j].y * scale));
            asm("cvt.rna.tf32.f32 %0, %1;" : "=r"(o0.w) : "f"(w[j].y * scale));
            asm("cvt.rna.tf32.f32 %0, %1;" : "=r"(o1.x) : "f"(u[j].z * scale));
            asm("cvt.rna.tf32.f32 %0, %1;" : "=r"(o1.y) : "f"(w[j].z * scale));
            asm("cvt.rna.tf32.f32 %0, %1;" : "=r"(o1.z) : "f"(u[j].w * scale));
            asm("cvt.rna.tf32.f32 %0, %1;" : "=r"(o1.w) : "f"(w[j].w * scale));
            dst[2 * g] = o0;
            dst[2 * g + 1] = o1;
        }
    }
}

// ---- tf32 mma.sync wrapper ------------------------------------------------
__device__ __forceinline__ void mma_tf32(float* d, uint32_t a0, uint32_t a1,
                                         uint32_t a2, uint32_t a3,
                                         uint32_t b0, uint32_t b1) {
    asm volatile(
        "mma.sync.aligned.m16n8k8.row.col.f32.tf32.tf32.f32 "
        "{%0,%1,%2,%3}, {%4,%5,%6,%7}, {%8,%9}, {%0,%1,%2,%3};"
        : "+f"(d[0]), "+f"(d[1]), "+f"(d[2]), "+f"(d[3])
        : "r"(a0), "r"(a1), "r"(a2), "r"(a3), "r"(b0), "r"(b1));
}

// ---- K4: 128x128 HMMA tf32 GEMM, cp.async double buffer, fused min -------
// 8 warps: warp grid 2(M)x4(N), warp tile 64x32 = 4x4 m16n8k8 atoms.
__global__ void __launch_bounds__(NTHR, 2)
k4_mma_min(int D) {
    extern __shared__ float smem[];
    float* sA = smem;              // [2][SAE]
    float* sB = smem + 2 * SAE;    // [2][SAE]
    int* sFlab = (int*)(smem + 4 * SAE);

    const int NA = g_aCnt;
    const int NF = g_fCnt;
    const int by = blockIdx.y, bx = blockIdx.x;
    if (by * BM >= NA || bx * BN >= NF) return;

    const int tid = threadIdx.x;
    const int wid = tid >> 5;
    const int lane = tid & 31;
    const int qid = lane >> 2;
    const int qlane = lane & 3;
    const int wm = (wid & 1) * 64;
    const int wn = (wid >> 1) * 32;

    if (tid < BN) {
        int f = bx * BN + tid;
        sFlab[tid] = (f < NF) ? g_fLab[f] : -1;
    }

    // load geometry: thread covers rows m0+32*it (it=0..3), 16B column q4
    const int m0 = tid >> 3;        // 0..31
    const int q4 = (tid & 7) * 4;   // 0,4,...,28 (floats)
    int aRowG[4], bRowG[4];
    #pragma unroll
    for (int it = 0; it < 4; it++) {
        int ga = by * BM + m0 + 32 * it;
        aRowG[it] = (ga < NA) ? ga : NA - 1;   // clamp; rows >= NA unused
        int gf = bx * BN + m0 + 32 * it;
        bRowG[it] = (gf < NF) ? gf : NF - 1;   // clamp; excluded via sFlab
    }
    const uint32_t sa0 = smem_u32(sA);
    const uint32_t sb0 = smem_u32(sB);
    const uint32_t dstOff = (uint32_t)((m0 * ASTR + q4) * 4);

    float acc[4][4][4];
    #pragma unroll
    for (int mi = 0; mi < 4; mi++)
        #pragma unroll
        for (int ni = 0; ni < 4; ni++)
            #pragma unroll
            for (int r = 0; r < 4; r++) acc[mi][ni][r] = 0.f;

    const int nch = D >> 5;

    // prefetch chunk 0 -> buffer 0
    #pragma unroll
    for (int it = 0; it < 4; it++) {
        cpa16(sa0 + dstOff + it * (32 * ASTR * 4),
              &g_A[(size_t)aRowG[it] * D + q4]);
        cpa16(sb0 + dstOff + it * (32 * ASTR * 4),
              &g_F[(size_t)bRowG[it] * D + q4]);
    }
    asm volatile("cp.async.commit_group;");

    for (int c = 0; c < nch; c++) {
        const int cur = c & 1;
        asm volatile("cp.async.wait_group 0;");
        __syncthreads();            // all warps: chunk c ready, chunk c-1 compute done
        if (c + 1 < nch) {          // prefetch c+1 into the other buffer (safe post-barrier)
            const int nb = (c + 1) & 1;
            const int ko = (c + 1) << 5;
            #pragma unroll
            for (int it = 0; it < 4; it++) {
                cpa16(sa0 + nb * (SAE * 4) + dstOff + it * (32 * ASTR * 4),
                      &g_A[(size_t)aRowG[it] * D + q4 + ko]);
                cpa16(sb0 + nb * (SAE * 4) + dstOff + it * (32 * ASTR * 4),
                      &g_F[(size_t)bRowG[it] * D + q4 + ko]);
            }
            asm volatile("cp.async.commit_group;");
        }

        const float* cA = sA + cur * SAE;
        const float* cB = sB + cur * SAE;
        #pragma unroll
        for (int g = 0; g < 4; g++) {
            const int kb2 = g * 8 + 2 * qlane;    // permuted offset of (k, k+4)
            uint32_t a[4][4], b[4][2];
            #pragma unroll
            for (int mi = 0; mi < 4; mi++) {
                const float* pr = cA + (wm + mi * 16 + qid) * ASTR + kb2;
                uint2 lo = *(const uint2*)pr;                  // a0, a2
                uint2 hi = *(const uint2*)(pr + 8 * ASTR);     // a1, a3
                a[mi][0] = lo.x; a[mi][1] = hi.x;
                a[mi][2] = lo.y; a[mi][3] = hi.y;
            }
            #pragma unroll
            for (int ni = 0; ni < 4; ni++) {
                const float* pr = cB + (wn + ni * 8 + qid) * ASTR + kb2;
                uint2 bb = *(const uint2*)pr;                  // b0, b1
                b[ni][0] = bb.x; b[ni][1] = bb.y;
            }
            #pragma unroll
            for (int mi = 0; mi < 4; mi++)
                #pragma unroll
                for (int ni = 0; ni < 4; ni++)
                    mma_tf32(acc[mi][ni], a[mi][0], a[mi][1], a[mi][2], a[mi][3],
                             b[ni][0], b[ni][1]);
        }
    }

    // --- epilogue: d^2 = max(2 - 2*dot, 0), masked min per anchor row ----
    int al[4][2];
    #pragma unroll
    for (int mi = 0; mi < 4; mi++)
        #pragma unroll
        for (int h = 0; h < 2; h++) {
            int a_ = by * BM + wm + mi * 16 + qid + h * 8;
            al[mi][h] = (a_ < NA) ? g_aLab[a_] : -2;
        }
    float posm[4][2], negm[4][2];
    #pragma unroll
    for (int mi = 0; mi < 4; mi++)
        #pragma unroll
        for (int h = 0; h < 2; h++) {
            posm[mi][h] = __uint_as_float(INFBITS);
            negm[mi][h] = posm[mi][h];
        }

    #pragma unroll
    for (int mi = 0; mi < 4; mi++) {
        #pragma unroll
        for (int ni = 0; ni < 4; ni++) {
            int n0 = wn + ni * 8 + 2 * qlane;
            int fl0 = sFlab[n0];
            int fl1 = sFlab[n0 + 1];
            #pragma unroll
            for (int h = 0; h < 2; h++) {
                float d20 = fmaxf(fmaf(-2.f, acc[mi][ni][h * 2 + 0], 2.f), 0.f);
                float d21 = fmaxf(fmaf(-2.f, acc[mi][ni][h * 2 + 1], 2.f), 0.f);
                int a_l = al[mi][h];
                if (fl0 >= 0) {
                    if (fl0 == a_l) posm[mi][h] = fminf(posm[mi][h], d20);
                    else            negm[mi][h] = fminf(negm[mi][h], d20);
                }
                if (fl1 >= 0) {
                    if (fl1 == a_l) posm[mi][h] = fminf(posm[mi][h], d21);
                    else            negm[mi][h] = fminf(negm[mi][h], d21);
                }
            }
        }
    }
    #pragma unroll
    for (int o = 1; o < 4; o <<= 1) {
        #pragma unroll
        for (int mi = 0; mi < 4; mi++)
            #pragma unroll
            for (int h = 0; h < 2; h++) {
                posm[mi][h] = fminf(posm[mi][h],
                                    __shfl_xor_sync(0xffffffffu, posm[mi][h], o));
                negm[mi][h] = fminf(negm[mi][h],
                                    __shfl_xor_sync(0xffffffffu, negm[mi][h], o));
            }
    }
    if (qlane == 0) {
        #pragma unroll
        for (int mi = 0; mi < 4; mi++)
            #pragma unroll
            for (int h = 0; h < 2; h++) {
                int a_ = by * BM + wm + mi * 16 + qid + h * 8;
                if (a_ < NA) {
                    atomicMin(&g_posBits[a_], __float_as_uint(posm[mi][h]));
                    atomicMin(&g_negBits[a_], __float_as_uint(negm[mi][h]));
                }
            }
    }
}

// ---- K5: finalize --------------------------------------------------------
__global__ void k5_finalize(float* __restrict__ out) {
    int n = g_aCnt;
    int tid = threadIdx.x;
    float sum = 0.f, cnt = 0.f;
    for (int i = tid; i < n; i += blockDim.x) {
        unsigned pb = g_posBits[i];
        unsigned nb = g_negBits[i];
        if (pb < INFBITS && nb < INFBITS) {
            float tl = fmaxf(sqrtf(__uint_as_float(pb)) -
                             sqrtf(__uint_as_float(nb)) + 0.3f, 0.f);
            sum += tl;
            cnt += 1.f;
        }
    }
    __shared__ float rs[8], rc[8];
    #pragma unroll
    for (int o = 16; o; o >>= 1) {
        sum += __shfl_xor_sync(0xffffffffu, sum, o);
        cnt += __shfl_xor_sync(0xffffffffu, cnt, o);
    }
    if ((tid & 31) == 0) { rs[tid >> 5] = sum; rc[tid >> 5] = cnt; }
    __syncthreads();
    if (tid == 0) {
        float s = 0.f, c = 0.f;
        #pragma unroll
        for (int w = 0; w < 8; w++) { s += rs[w]; c += rc[w]; }
        out[0] = (c > 0.f) ? s / fmaxf(c, 1.f) : 0.f;
    }
}

// ---------------------------------------------------------------------------
extern "C" void kernel_launch(void* const* d_in, const int* in_sizes, int n_in,
                              void* d_out, int out_size) {
    const float* feat  = (const float*)d_in[0];
    const void* labels = d_in[1];
    const void* doms   = d_in[2];
    int B = in_sizes[1];
    int D = in_sizes[0] / B;

    static int smem_set = 0;
    if (!smem_set) {
        cudaFuncSetAttribute(k4_mma_min,
                             cudaFuncAttributeMaxDynamicSharedMemorySize,
                             SMEM4_BYTES);
        smem_set = 1;
    }

    k0_reset<<<1, 1>>>();
    k1_init_detect<<<(B + 255) / 256, 256>>>((const unsigned*)labels, B);
    k2_partition<<<(B + 255) / 256, 256>>>(labels, doms, B);
    k3_normalize<<<dim3((B + 7) / 8, 2), 256>>>(feat, D);
    dim3 grid((B + BN - 1) / BN, (B + BM - 1) / BM);  // worst-case NA/NF
    k4_mma_min<<<grid, NTHR, SMEM4_BYTES>>>(D);
    k5_finalize<<<1, 256>>>((float*)d_out);
}

// round 11
// speedup vs baseline: 1.5332x; 1.5332x over previous
#include <cuda_runtime.h>
#include <stdint.h>

// ---------------------------------------------------------------------------
// TripletContrastiveLoss — tf32 mma.sync, 128x128 tile, occ-2, cp.async
// double buffer (R8 loop structure), permuted-K layout + LDS.64 fragments.
// (tcgen05 unavailable: bench PTX targets compute_103 w/o 'a'.)
// ---------------------------------------------------------------------------

#define BMAX 8192
#define DMAX 1024
#define INFBITS 0x7f800000u

#define BM 128
#define BN 128
#define BK 32
#define ASTR 40      // row stride (floats); LDS.64 2-phase = full crossbar BW
#define NTHR 256
#define SAE (BM * ASTR)                    // 5120 floats per buffer
#define SMEM4_BYTES (4 * SAE * 4 + BN * 4) // 2 stages x (A+B) + labels = 82432 B

// K-permutation: each 8-float K-group stored as (k0,k4,k1,k5,k2,k6,k3,k7);
// mma fragment pair (k, k+4) sits at float offset g*8 + 2*(k%4), 8B-contiguous.
__device__ float g_A[(size_t)BMAX * DMAX];   // normalized anchors (tf32, K-permuted)
__device__ float g_F[(size_t)BMAX * DMAX];   // normalized fields  (tf32, K-permuted)
__device__ int   g_aRow[BMAX];
__device__ int   g_fRow[BMAX];
__device__ int   g_aLab[BMAX];
__device__ int   g_fLab[BMAX];
__device__ int   g_aCnt;
__device__ int   g_fCnt;
__device__ unsigned g_posBits[BMAX];
__device__ unsigned g_negBits[BMAX];
__device__ int   g_is64;

__device__ __forceinline__ uint32_t smem_u32(const void* p) {
    uint32_t a;
    asm("{ .reg .u64 t; cvta.to.shared.u64 t, %1; cvt.u32.u64 %0, t; }"
        : "=r"(a) : "l"(p));
    return a;
}
__device__ __forceinline__ void cpa16(uint32_t dst, const void* src) {
    asm volatile("cp.async.cg.shared.global [%0], [%1], 16;"
                 :: "r"(dst), "l"(src));
}

// ---- K0: reset scalars --------------------------------------------------
__global__ void k0_reset() {
    g_aCnt = 0;
    g_fCnt = 0;
    g_is64 = 1;
}

// ---- K1: init min arrays + label dtype detection ------------------------
// int64 labels (<2^31): every odd 32-bit word is 0. int32: some odd word !=0.
__global__ void k1_init_detect(const unsigned* __restrict__ labw, int B) {
    int i = blockIdx.x * blockDim.x + threadIdx.x;
    if (i < B) {
        g_posBits[i] = INFBITS;
        g_negBits[i] = INFBITS;
        if ((i & 1) && labw[i] != 0u) g_is64 = 0;
    }
}

// ---- K2: partition into compact anchor/field lists ----------------------
__global__ void k2_partition(const void* __restrict__ labels,
                             const void* __restrict__ doms, int B) {
    int i = blockIdx.x * blockDim.x + threadIdx.x;
    if (i >= B) return;
    int is64 = g_is64;
    long long dom, lab;
    if (is64) {
        dom = ((const long long*)doms)[i];
        lab = ((const long long*)labels)[i];
    } else {
        dom = ((const int*)doms)[i];
        lab = ((const int*)labels)[i];
    }
    if (dom == 0) {
        int p = atomicAdd(&g_aCnt, 1);
        g_aRow[p] = i;
        g_aLab[p] = (int)lab;
    } else if (dom == 1) {
        int p = atomicAdd(&g_fCnt, 1);
        g_fRow[p] = i;
        g_fLab[p] = (int)lab;
    }
}

// ---- K3: normalize + tf32 round + K-permute, one warp per row -----------
// Coalesced reads/writes; even/odd lane pairs swap float4s via shfl so each
// lane emits the permuted float4 for its own (coalesced) output slot.
__global__ void k3_normalize(const float* __restrict__ feat, int D) {
    int side = blockIdx.y;
    int n = side ? g_fCnt : g_aCnt;
    int warp = threadIdx.x >> 5;
    int lane = threadIdx.x & 31;
    int b = blockIdx.x * 8 + warp;
    if (b >= n) return;
    int row = side ? g_fRow[b] : g_aRow[b];
    const float4* src = (const float4*)(feat + (size_t)row * D);
    uint4* dst = (uint4*)((side ? g_F : g_A) + (size_t)b * D);
    int nv = D >> 2;                  // <= 256 float4 slots

    float4 v[8];
    float s = 0.f;
    #pragma unroll
    for (int j = 0; j < 8; j++) {
        int t = lane + j * 32;
        if (t < nv) {
            v[j] = src[t];
            s += v[j].x * v[j].x + v[j].y * v[j].y +
                 v[j].z * v[j].z + v[j].w * v[j].w;
        }
    }
    #pragma unroll
    for (int o = 16; o; o >>= 1) s += __shfl_xor_sync(0xffffffffu, s, o);
    float scale = 1.f / fmaxf(sqrtf(s), 1e-12f);

    const bool even = (lane & 1) == 0;
    #pragma unroll
    for (int j = 0; j < 8; j++) {
        int t = lane + j * 32;
        if (t < nv) {
            float4 p;
            p.x = __shfl_xor_sync(0xffffffffu, v[j].x, 1);
            p.y = __shfl_xor_sync(0xffffffffu, v[j].y, 1);
            p.z = __shfl_xor_sync(0xffffffffu, v[j].z, 1);
            p.w = __shfl_xor_sync(0xffffffffu, v[j].w, 1);
            // e = group floats k0..k3, o4 = k4..k7
            float4 e  = even ? v[j] : p;
            float4 o4 = even ? p : v[j];
            // out_even = (k0,k4,k1,k5); out_odd = (k2,k6,k3,k7)
            float f0 = even ? e.x : e.z;
            float f1 = even ? o4.x : o4.z;
            float f2 = even ? e.y : e.w;
            float f3 = even ? o4.y : o4.w;
            uint4 o;
            asm("cvt.rna.tf32.f32 %0, %1;" : "=r"(o.x) : "f"(f0 * scale));
            asm("cvt.rna.tf32.f32 %0, %1;" : "=r"(o.y) : "f"(f1 * scale));
            asm("cvt.rna.tf32.f32 %0, %1;" : "=r"(o.z) : "f"(f2 * scale));
            asm("cvt.rna.tf32.f32 %0, %1;" : "=r"(o.w) : "f"(f3 * scale));
            dst[t] = o;
        }
    }
}

// ---- tf32 mma.sync wrapper ------------------------------------------------
__device__ __forceinline__ void mma_tf32(float* d, uint32_t a0, uint32_t a1,
                                         uint32_t a2, uint32_t a3,
                                         uint32_t b0, uint32_t b1) {
    asm volatile(
        "mma.sync.aligned.m16n8k8.row.col.f32.tf32.tf32.f32 "
        "{%0,%1,%2,%3}, {%4,%5,%6,%7}, {%8,%9}, {%0,%1,%2,%3};"
        : "+f"(d[0]), "+f"(d[1]), "+f"(d[2]), "+f"(d[3])
        : "r"(a0), "r"(a1), "r"(a2), "r"(a3), "r"(b0), "r"(b1));
}

// ---- K4: 128x128 HMMA tf32 GEMM, cp.async double buffer, fused min -------
// 8 warps: warp grid 2(M)x4(N), warp tile 64x32 = 4x4 m16n8k8 atoms.
// Loop structure identical to the 237.6us R8 kernel; only the fragment
// loads changed (uint2 at permuted offsets).
__global__ void __launch_bounds__(NTHR, 2)
k4_mma_min(int D) {
    extern __shared__ float smem[];
    float* sA = smem;              // [2][SAE]
    float* sB = smem + 2 * SAE;    // [2][SAE]
    int* sFlab = (int*)(smem + 4 * SAE);

    const int NA = g_aCnt;
    const int NF = g_fCnt;
    const int by = blockIdx.y, bx = blockIdx.x;
    if (by * BM >= NA || bx * BN >= NF) return;

    const int tid = threadIdx.x;
    const int wid = tid >> 5;
    const int lane = tid & 31;
    const int qid = lane >> 2;
    const int qlane = lane & 3;
    const int wm = (wid & 1) * 64;
    const int wn = (wid >> 1) * 32;

    if (tid < BN) {
        int f = bx * BN + tid;
        sFlab[tid] = (f < NF) ? g_fLab[f] : -1;
    }

    // load geometry: thread covers rows m0+32*it (it=0..3), 16B column q4
    const int m0 = tid >> 3;        // 0..31
    const int q4 = (tid & 7) * 4;   // 0,4,...,28 (floats)
    int aRowG[4], bRowG[4];
    #pragma unroll
    for (int it = 0; it < 4; it++) {
        int ga = by * BM + m0 + 32 * it;
        aRowG[it] = (ga < NA) ? ga : NA - 1;   // clamp; rows >= NA unused
        int gf = bx * BN + m0 + 32 * it;
        bRowG[it] = (gf < NF) ? gf : NF - 1;   // clamp; excluded via sFlab
    }
    const uint32_t sa0 = smem_u32(sA);
    const uint32_t sb0 = smem_u32(sB);
    const uint32_t dstOff = (uint32_t)((m0 * ASTR + q4) * 4);

    float acc[4][4][4];
    #pragma unroll
    for (int mi = 0; mi < 4; mi++)
        #pragma unroll
        for (int ni = 0; ni < 4; ni++)
            #pragma unroll
            for (int r = 0; r < 4; r++) acc[mi][ni][r] = 0.f;

    const int nch = D >> 5;

    // prefetch chunk 0 -> buffer 0
    #pragma unroll
    for (int it = 0; it < 4; it++) {
        cpa16(sa0 + dstOff + it * (32 * ASTR * 4),
              &g_A[(size_t)aRowG[it] * D + q4]);
        cpa16(sb0 + dstOff + it * (32 * ASTR * 4),
              &g_F[(size_t)bRowG[it] * D + q4]);
    }
    asm volatile("cp.async.commit_group;");

    for (int c = 0; c < nch; c++) {
        const int cur = c & 1;
        if (c + 1 < nch) {
            const int nb = (c + 1) & 1;
            const int ko = (c + 1) << 5;
            #pragma unroll
            for (int it = 0; it < 4; it++) {
                cpa16(sa0 + nb * (SAE * 4) + dstOff + it * (32 * ASTR * 4),
                      &g_A[(size_t)aRowG[it] * D + q4 + ko]);
                cpa16(sb0 + nb * (SAE * 4) + dstOff + it * (32 * ASTR * 4),
                      &g_F[(size_t)bRowG[it] * D + q4 + ko]);
            }
            asm volatile("cp.async.commit_group;");
            asm volatile("cp.async.wait_group 1;");
        } else {
            asm volatile("cp.async.wait_group 0;");
        }
        __syncthreads();

        const float* cA = sA + cur * SAE;
        const float* cB = sB + cur * SAE;
        #pragma unroll
        for (int g = 0; g < 4; g++) {
            const int kb2 = g * 8 + 2 * qlane;    // permuted offset of (k, k+4)
            uint32_t a[4][4], b[4][2];
            #pragma unroll
            for (int mi = 0; mi < 4; mi++) {
                const float* pr = cA + (wm + mi * 16 + qid) * ASTR + kb2;
                uint2 lo = *(const uint2*)pr;                  // a0, a2
                uint2 hi = *(const uint2*)(pr + 8 * ASTR);     // a1, a3
                a[mi][0] = lo.x; a[mi][1] = hi.x;
                a[mi][2] = lo.y; a[mi][3] = hi.y;
            }
            #pragma unroll
            for (int ni = 0; ni < 4; ni++) {
                const float* pr = cB + (wn + ni * 8 + qid) * ASTR + kb2;
                uint2 bb = *(const uint2*)pr;                  // b0, b1
                b[ni][0] = bb.x; b[ni][1] = bb.y;
            }
            #pragma unroll
            for (int mi = 0; mi < 4; mi++)
                #pragma unroll
                for (int ni = 0; ni < 4; ni++)
                    mma_tf32(acc[mi][ni], a[mi][0], a[mi][1], a[mi][2], a[mi][3],
                             b[ni][0], b[ni][1]);
        }
        __syncthreads();   // fragment reads done before buffer reuse
    }

    // --- epilogue: d^2 = max(2 - 2*dot, 0), masked min per anchor row ----
    int al[4][2];
    #pragma unroll
    for (int mi = 0; mi < 4; mi++)
        #pragma unroll
        for (int h = 0; h < 2; h++) {
            int a_ = by * BM + wm + mi * 16 + qid + h * 8;
            al[mi][h] = (a_ < NA) ? g_aLab[a_] : -2;
        }
    float posm[4][2], negm[4][2];
    #pragma unroll
    for (int mi = 0; mi < 4; mi++)
        #pragma unroll
        for (int h = 0; h < 2; h++) {
            posm[mi][h] = __uint_as_float(INFBITS);
            negm[mi][h] = posm[mi][h];
        }

    #pragma unroll
    for (int mi = 0; mi < 4; mi++) {
        #pragma unroll
        for (int ni = 0; ni < 4; ni++) {
            int n0 = wn + ni * 8 + 2 * qlane;
            int fl0 = sFlab[n0];
            int fl1 = sFlab[n0 + 1];
            #pragma unroll
            for (int h = 0; h < 2; h++) {
                float d20 = fmaxf(fmaf(-2.f, acc[mi][ni][h * 2 + 0], 2.f), 0.f);
                float d21 = fmaxf(fmaf(-2.f, acc[mi][ni][h * 2 + 1], 2.f), 0.f);
                int a_l = al[mi][h];
                if (fl0 >= 0) {
                    if (fl0 == a_l) posm[mi][h] = fminf(posm[mi][h], d20);
                    else            negm[mi][h] = fminf(negm[mi][h], d20);
                }
                if (fl1 >= 0) {
                    if (fl1 == a_l) posm[mi][h] = fminf(posm[mi][h], d21);
                    else            negm[mi][h] = fminf(negm[mi][h], d21);
                }
            }
        }
    }
    #pragma unroll
    for (int o = 1; o < 4; o <<= 1) {
        #pragma unroll
        for (int mi = 0; mi < 4; mi++)
            #pragma unroll
            for (int h = 0; h < 2; h++) {
                posm[mi][h] = fminf(posm[mi][h],
                                    __shfl_xor_sync(0xffffffffu, posm[mi][h], o));
                negm[mi][h] = fminf(negm[mi][h],
                                    __shfl_xor_sync(0xffffffffu, negm[mi][h], o));
            }
    }
    if (qlane == 0) {
        #pragma unroll
        for (int mi = 0; mi < 4; mi++)
            #pragma unroll
            for (int h = 0; h < 2; h++) {
                int a_ = by * BM + wm + mi * 16 + qid + h * 8;
                if (a_ < NA) {
                    atomicMin(&g_posBits[a_], __float_as_uint(posm[mi][h]));
                    atomicMin(&g_negBits[a_], __float_as_uint(negm[mi][h]));
                }
            }
    }
}

// ---- K5: finalize --------------------------------------------------------
__global__ void k5_finalize(float* __restrict__ out) {
    int n = g_aCnt;
    int tid = threadIdx.x;
    float sum = 0.f, cnt = 0.f;
    for (int i = tid; i < n; i += blockDim.x) {
        unsigned pb = g_posBits[i];
        unsigned nb = g_negBits[i];
        if (pb < INFBITS && nb < INFBITS) {
            float tl = fmaxf(sqrtf(__uint_as_float(pb)) -
                             sqrtf(__uint_as_float(nb)) + 0.3f, 0.f);
            sum += tl;
            cnt += 1.f;
        }
    }
    __shared__ float rs[8], rc[8];
    #pragma unroll
    for (int o = 16; o; o >>= 1) {
        sum += __shfl_xor_sync(0xffffffffu, sum, o);
        cnt += __shfl_xor_sync(0xffffffffu, cnt, o);
    }
    if ((tid & 31) == 0) { rs[tid >> 5] = sum; rc[tid >> 5] = cnt; }
    __syncthreads();
    if (tid == 0) {
        float s = 0.f, c = 0.f;
        #pragma unroll
        for (int w = 0; w < 8; w++) { s += rs[w]; c += rc[w]; }
        out[0] = (c > 0.f) ? s / fmaxf(c, 1.f) : 0.f;
    }
}

// ---------------------------------------------------------------------------
extern "C" void kernel_launch(void* const* d_in, const int* in_sizes, int n_in,
                              void* d_out, int out_size) {
    const float* feat  = (const float*)d_in[0];
    const void* labels = d_in[1];
    const void* doms   = d_in[2];
    int B = in_sizes[1];
    int D = in_sizes[0] / B;

    static int smem_set = 0;
    if (!smem_set) {
        cudaFuncSetAttribute(k4_mma_min,
                             cudaFuncAttributeMaxDynamicSharedMemorySize,
                             SMEM4_BYTES);
        smem_set = 1;
    }

    k0_reset<<<1, 1>>>();
    k1_init_detect<<<(B + 255) / 256, 256>>>((const unsigned*)labels, B);
    k2_partition<<<(B + 255) / 256, 256>>>(labels, doms, B);
    k3_normalize<<<dim3((B + 7) / 8, 2), 256>>>(feat, D);
    dim3 grid((B + BN - 1) / BN, (B + BM - 1) / BM);  // worst-case NA/NF
    k4_mma_min<<<grid, NTHR, SMEM4_BYTES>>>(D);
    k5_finalize<<<1, 256>>>((float*)d_out);
}